// round 11
// baseline (speedup 1.0000x reference)
#include <cuda_runtime.h>

// KANLayer_60464549593380 on GB300 (sm_103a):
//   out[b] = sum_d P_d(tanh(x[b,d])), P_d = degree-8 monomial poly from
//   w = hweights @ coeffs (summation reorder + Chebyshev->monomial fold).
// R7: coalesced LDG (lane = (row-of-pair, pos-in-quarter): 4 lines/warp-LDG),
// coeffs in registers (lane owns 4 fixed dims), no loop barriers, 4-shfl
// half-warp reduce. Packed f32x2 tanh + Horner.

#define DEG   8
#define NF    9
#define DDIM  256
#define FDIM  2304
#define F4DIM 576
#define ROWS  64            // rows per block

__device__ float g_w[FDIM];

typedef unsigned long long u64;

// ---------------- packed f32x2 / MUFU helpers ----------------
__device__ __forceinline__ u64 fma2(u64 a, u64 b, u64 c) {
    u64 d; asm("fma.rn.f32x2 %0, %1, %2, %3;" : "=l"(d) : "l"(a), "l"(b), "l"(c));
    return d;
}
__device__ __forceinline__ u64 add2(u64 a, u64 b) {
    u64 d; asm("add.rn.f32x2 %0, %1, %2;" : "=l"(d) : "l"(a), "l"(b));
    return d;
}
__device__ __forceinline__ u64 mul2(u64 a, u64 b) {
    u64 d; asm("mul.rn.f32x2 %0, %1, %2;" : "=l"(d) : "l"(a), "l"(b));
    return d;
}
__device__ __forceinline__ u64 pack2(float lo, float hi) {
    u64 d; asm("mov.b64 %0, {%1, %2};" : "=l"(d) : "f"(lo), "f"(hi));
    return d;
}
__device__ __forceinline__ float unpack_sum(u64 v) {
    float lo, hi;
    asm("mov.b64 {%0, %1}, %2;" : "=f"(lo), "=f"(hi) : "l"(v));
    return lo + hi;
}
__device__ __forceinline__ float ex2a(float v) {
    float r; asm("ex2.approx.ftz.f32 %0, %1;" : "=f"(r) : "f"(v)); return r;
}
__device__ __forceinline__ float rcpa(float v) {
    float r; asm("rcp.approx.ftz.f32 %0, %1;" : "=f"(r) : "f"(v)); return r;
}

// Packed tanh of 2 values: t = (1-e)/(1+e), e = exp(-2v).
__device__ __forceinline__ u64 tanh2(u64 v2) {
    const u64 ONE2  = 0x3f8000003f800000ull;   // (1.0f, 1.0f)
    const u64 NEG12 = 0xbf800000bf800000ull;   // (-1.0f, -1.0f)
    const u64 SC2   = 0xc038aa3bc038aa3bull;   // (-2*log2e) x2
    u64 s2 = mul2(v2, SC2);
    float slo, shi;
    asm("mov.b64 {%0, %1}, %2;" : "=f"(slo), "=f"(shi) : "l"(s2));
    u64 e2 = pack2(ex2a(slo), ex2a(shi));
    u64 num = fma2(e2, NEG12, ONE2);           // 1 - e
    u64 den = add2(e2, ONE2);                  // 1 + e
    float dlo, dhi;
    asm("mov.b64 {%0, %1}, %2;" : "=f"(dlo), "=f"(dhi) : "l"(den));
    u64 r2 = pack2(rcpa(dlo), rcpa(dhi));
    return mul2(num, r2);
}

// ---------------- Prep: w[f] = sum_n hw[n]*coeffs[n,f] ----------------
__global__ void k_wprep(const float4* __restrict__ c4,
                        const float* __restrict__ hw, int N) {
    __shared__ float4 red[128];
    const int col = blockIdx.x;
    const int t   = threadIdx.x;
    float4 s = make_float4(0.f, 0.f, 0.f, 0.f);
    for (int n = t; n < N; n += 128) {
        float  h = hw[n];
        float4 v = c4[(size_t)n * F4DIM + col];
        s.x = fmaf(h, v.x, s.x);
        s.y = fmaf(h, v.y, s.y);
        s.z = fmaf(h, v.z, s.z);
        s.w = fmaf(h, v.w, s.w);
    }
    red[t] = s;
    __syncthreads();
    #pragma unroll
    for (int o = 64; o >= 1; o >>= 1) {
        if (t < o) {
            float4 b = red[t + o];
            red[t].x += b.x; red[t].y += b.y; red[t].z += b.z; red[t].w += b.w;
        }
        __syncthreads();
    }
    if (t == 0) ((float4*)g_w)[col] = red[0];
}

// Chebyshev -> monomial for one dim's 9 weights.
__device__ __forceinline__ void cheb2mono(const float* __restrict__ w, float* a) {
    a[0] = w[0] - w[2] + w[4] - w[6] + w[8];
    a[1] = w[1] - 3.f * w[3] + 5.f * w[5] - 7.f * w[7];
    a[2] = 2.f * w[2] - 8.f * w[4] + 18.f * w[6] - 32.f * w[8];
    a[3] = 4.f * w[3] - 20.f * w[5] + 56.f * w[7];
    a[4] = 8.f * w[4] - 48.f * w[6] + 160.f * w[8];
    a[5] = 16.f * w[5] - 112.f * w[7];
    a[6] = 32.f * w[6] - 256.f * w[8];
    a[7] = 64.f * w[7];
    a[8] = 128.f * w[8];
}

// ---------------- Main ----------------
// 256 threads = 8 warps. Warp w: quarter q = w&3 (dims 64q..64q+63),
// row group g = w>>2 (rows 32g..32g+31 of block). Lane: sub = lane>>4
// (row of pair), li = lane&15 (4-dim slot: dims 64q+4li..+3).
// Iter i handles rows 32g+2i, 32g+2i+1. One float4 LDG per lane per iter:
// half-warps read 2x256B contiguous -> 4 lines/warp-LDG.
__global__ void __launch_bounds__(256)
k_main(const float* __restrict__ x, float* __restrict__ out, int B) {
    __shared__ float part[ROWS][4];
    const int t    = threadIdx.x;
    const int lane = t & 31;
    const int w    = t >> 5;
    const int q    = w & 3;
    const int g    = w >> 2;
    const int sub  = lane >> 4;
    const int li   = lane & 15;
    const size_t row0 = (size_t)blockIdx.x * ROWS;

    // Coefficients for this lane's 4 dims (d0..d0+3), packed as 2 chains.
    u64 c0[NF], c1[NF];
    {
        const int d0 = 64 * q + 4 * li;
        float wb[4 * NF];                       // 36 consecutive floats, 16B-aligned
        const float4* wp = (const float4*)(g_w + d0 * NF);
        #pragma unroll
        for (int k = 0; k < 9; ++k) ((float4*)wb)[k] = wp[k];
        float a0[NF], a1[NF], a2[NF], a3[NF];
        cheb2mono(wb +  0, a0);
        cheb2mono(wb +  9, a1);
        cheb2mono(wb + 18, a2);
        cheb2mono(wb + 27, a3);
        #pragma unroll
        for (int j = 0; j < NF; ++j) {
            c0[j] = pack2(a0[j], a1[j]);
            c1[j] = pack2(a2[j], a3[j]);
        }
    }

    // float4 index of this lane's slice for iteration i:
    //   row = row0 + 32g + 2i + sub;  offset = row*64 + 16q + li
    const float4* xp = (const float4*)x;
    size_t idx = (row0 + 32 * g + sub) * 64 + 16 * q + li;

    float4 xv = xp[idx];
    #pragma unroll
    for (int i = 0; i < 16; ++i) {
        float4 xn;
        if (i < 15) xn = xp[idx + (size_t)(i + 1) * 128];

        u64 t0 = tanh2(pack2(xv.x, xv.y));
        u64 t1 = tanh2(pack2(xv.z, xv.w));
        u64 h0 = c0[DEG], h1 = c1[DEG];
        #pragma unroll
        for (int j = DEG - 1; j >= 0; --j) {
            h0 = fma2(t0, h0, c0[j]);
            h1 = fma2(t1, h1, c1[j]);
        }
        float s = unpack_sum(add2(h0, h1));

        // Reduce over the 16-lane half (xor of bits 0..3 stays in-half).
        s += __shfl_xor_sync(0xffffffffu, s, 1);
        s += __shfl_xor_sync(0xffffffffu, s, 2);
        s += __shfl_xor_sync(0xffffffffu, s, 4);
        s += __shfl_xor_sync(0xffffffffu, s, 8);
        if (li == 0) part[32 * g + 2 * i + sub][q] = s;

        xv = xn;
    }

    __syncthreads();
    if (t < ROWS) {
        float4 p = *(const float4*)part[t];
        size_t row = row0 + t;
        if (row < (size_t)B) out[row] = (p.x + p.y) + (p.z + p.w);
    }
}

extern "C" void kernel_launch(void* const* d_in, const int* in_sizes, int n_in,
                              void* d_out, int out_size) {
    const float* x      = (const float*)d_in[0];
    const float* coeffs = (const float*)d_in[1];
    const float* hw     = (const float*)d_in[2];
    float* out = (float*)d_out;

    const int B = out_size;       // 32768 = 512 * 64
    const int N = in_sizes[2];    // 256

    k_wprep<<<F4DIM, 128>>>((const float4*)coeffs, hw, N);
    k_main<<<(B + ROWS - 1) / ROWS, 256>>>(x, out, B);
}

// round 13
// speedup vs baseline: 1.1359x; 1.1359x over previous
#include <cuda_runtime.h>

// KANLayer_60464549593380 on GB300 (sm_103a):
//   out[b] = sum_d P_d(tanh(x[b,d])), P_d = degree-8 monomial poly from
//   w = hweights @ coeffs (summation reorder + Chebyshev->monomial fold).
// R13 = R8 (occupancy-first: 2 dims/lane, 8192 warps, coalesced LDG.64,
// shuffle-free loop) with the partial-buffer collision FIXED:
// part[row][32q+lane] (128 partials per row), two-step tail reduction.

#define DEG   8
#define NF    9
#define DDIM  256
#define FDIM  2304
#define F4DIM 576
#define ROWS  32            // rows per block
#define PPITCH 129          // part[] pitch in floats

__device__ float g_w[FDIM];

typedef unsigned long long u64;

// ---------------- packed f32x2 / MUFU helpers ----------------
__device__ __forceinline__ u64 fma2(u64 a, u64 b, u64 c) {
    u64 d; asm("fma.rn.f32x2 %0, %1, %2, %3;" : "=l"(d) : "l"(a), "l"(b), "l"(c));
    return d;
}
__device__ __forceinline__ u64 add2(u64 a, u64 b) {
    u64 d; asm("add.rn.f32x2 %0, %1, %2;" : "=l"(d) : "l"(a), "l"(b));
    return d;
}
__device__ __forceinline__ u64 mul2(u64 a, u64 b) {
    u64 d; asm("mul.rn.f32x2 %0, %1, %2;" : "=l"(d) : "l"(a), "l"(b));
    return d;
}
__device__ __forceinline__ u64 pack2(float lo, float hi) {
    u64 d; asm("mov.b64 %0, {%1, %2};" : "=l"(d) : "f"(lo), "f"(hi));
    return d;
}
__device__ __forceinline__ float unpack_sum(u64 v) {
    float lo, hi;
    asm("mov.b64 {%0, %1}, %2;" : "=f"(lo), "=f"(hi) : "l"(v));
    return lo + hi;
}
__device__ __forceinline__ float ex2a(float v) {
    float r; asm("ex2.approx.ftz.f32 %0, %1;" : "=f"(r) : "f"(v)); return r;
}
__device__ __forceinline__ float rcpa(float v) {
    float r; asm("rcp.approx.ftz.f32 %0, %1;" : "=f"(r) : "f"(v)); return r;
}

// Packed tanh of 2 values: t = (1-e)/(1+e), e = exp(-2v).
__device__ __forceinline__ u64 tanh2(u64 v2) {
    const u64 ONE2  = 0x3f8000003f800000ull;   // (1.0f, 1.0f)
    const u64 NEG12 = 0xbf800000bf800000ull;   // (-1.0f, -1.0f)
    const u64 SC2   = 0xc038aa3bc038aa3bull;   // (-2*log2e) x2
    u64 s2 = mul2(v2, SC2);
    float slo, shi;
    asm("mov.b64 {%0, %1}, %2;" : "=f"(slo), "=f"(shi) : "l"(s2));
    u64 e2 = pack2(ex2a(slo), ex2a(shi));
    u64 num = fma2(e2, NEG12, ONE2);           // 1 - e
    u64 den = add2(e2, ONE2);                  // 1 + e
    float dlo, dhi;
    asm("mov.b64 {%0, %1}, %2;" : "=f"(dlo), "=f"(dhi) : "l"(den));
    u64 r2 = pack2(rcpa(dlo), rcpa(dhi));
    return mul2(num, r2);
}

// ---------------- Prep: w[f] = sum_n hw[n]*coeffs[n,f] ----------------
__global__ void k_wprep(const float4* __restrict__ c4,
                        const float* __restrict__ hw, int N) {
    __shared__ float4 red[128];
    const int col = blockIdx.x;
    const int t   = threadIdx.x;
    float4 s = make_float4(0.f, 0.f, 0.f, 0.f);
    for (int n = t; n < N; n += 128) {
        float  h = hw[n];
        float4 v = c4[(size_t)n * F4DIM + col];
        s.x = fmaf(h, v.x, s.x);
        s.y = fmaf(h, v.y, s.y);
        s.z = fmaf(h, v.z, s.z);
        s.w = fmaf(h, v.w, s.w);
    }
    red[t] = s;
    __syncthreads();
    #pragma unroll
    for (int o = 64; o >= 1; o >>= 1) {
        if (t < o) {
            float4 b = red[t + o];
            red[t].x += b.x; red[t].y += b.y; red[t].z += b.z; red[t].w += b.w;
        }
        __syncthreads();
    }
    if (t == 0) ((float4*)g_w)[col] = red[0];
}

// Chebyshev -> monomial for one dim's 9 weights.
__device__ __forceinline__ void cheb2mono(const float* __restrict__ w, float* a) {
    a[0] = w[0] - w[2] + w[4] - w[6] + w[8];
    a[1] = w[1] - 3.f * w[3] + 5.f * w[5] - 7.f * w[7];
    a[2] = 2.f * w[2] - 8.f * w[4] + 18.f * w[6] - 32.f * w[8];
    a[3] = 4.f * w[3] - 20.f * w[5] + 56.f * w[7];
    a[4] = 8.f * w[4] - 48.f * w[6] + 160.f * w[8];
    a[5] = 16.f * w[5] - 112.f * w[7];
    a[6] = 32.f * w[6] - 256.f * w[8];
    a[7] = 64.f * w[7];
    a[8] = 128.f * w[8];
}

// ---------------- Main ----------------
// 256 threads = 8 warps, 32 rows/block, grid 1024 (8192 warps total).
// Warp w: quarter q = w&3 (dims 64q..64q+63), row group g = w>>2
// (rows 16g..16g+15). Lane owns 2 fixed dims: d0 = 64q + 2*lane.
// Iter i: row 16g+i; lane reads x[row][d0..d0+1] (warp: 256B contiguous),
// evaluates its 2 polys (one packed Horner chain), stores its scalar
// partial to part[row][32q+lane]. No shuffles, no loop barriers.
__global__ void __launch_bounds__(256)
k_main(const float* __restrict__ x, float* __restrict__ out, int B) {
    __shared__ float part[ROWS][PPITCH];          // 16.5 KB
    __shared__ float red2[ROWS][9];               // 1.2 KB
    const int t    = threadIdx.x;
    const int lane = t & 31;
    const int w    = t >> 5;
    const int q    = w & 3;
    const int g    = w >> 2;
    const size_t row0 = (size_t)blockIdx.x * ROWS;

    // Coefficients for this lane's 2 dims, packed as one chain.
    u64 c[NF];
    {
        const int d0 = 64 * q + 2 * lane;
        const float2* wp = (const float2*)(g_w + d0 * NF);  // 18 floats, 8B-aligned
        float wb[2 * NF];
        #pragma unroll
        for (int k = 0; k < NF; ++k) ((float2*)wb)[k] = wp[k];
        float alo[NF], ahi[NF];
        cheb2mono(wb, alo);
        cheb2mono(wb + NF, ahi);
        #pragma unroll
        for (int j = 0; j < NF; ++j) c[j] = pack2(alo[j], ahi[j]);
    }

    // float2 index for iteration i: (row0 + 16g + i)*128 + 32q + lane.
    const float2* xp = (const float2*)x;
    size_t idx = (row0 + 16 * g) * 128 + 32 * q + lane;

    float2 xv = xp[idx];
    #pragma unroll
    for (int i = 0; i < 16; ++i) {
        float2 xn;
        if (i < 15) xn = xp[idx + (size_t)(i + 1) * 128];

        u64 tp = tanh2(pack2(xv.x, xv.y));
        u64 h  = c[DEG];
        #pragma unroll
        for (int j = DEG - 1; j >= 0; --j)
            h = fma2(tp, h, c[j]);
        part[16 * g + i][32 * q + lane] = unpack_sum(h);  // unique slot per warp

        xv = xn;
    }

    __syncthreads();
    // Tail reduce, step 1: 256 threads, each sums 16 of a row's 128 partials.
    {
        const int r = t >> 3, seg = t & 7;
        const float* pr = part[r] + 16 * seg;
        float s0 = 0.f, s1 = 0.f;
        #pragma unroll
        for (int k = 0; k < 16; k += 2) { s0 += pr[k]; s1 += pr[k + 1]; }
        red2[r][seg] = s0 + s1;
    }
    __syncthreads();
    // Step 2: 32 threads, each sums its row's 8 sub-partials.
    if (t < ROWS) {
        const float* rr = red2[t];
        float s = ((rr[0] + rr[1]) + (rr[2] + rr[3]))
                + ((rr[4] + rr[5]) + (rr[6] + rr[7]));
        size_t row = row0 + t;
        if (row < (size_t)B) out[row] = s;
    }
}

extern "C" void kernel_launch(void* const* d_in, const int* in_sizes, int n_in,
                              void* d_out, int out_size) {
    const float* x      = (const float*)d_in[0];
    const float* coeffs = (const float*)d_in[1];
    const float* hw     = (const float*)d_in[2];
    float* out = (float*)d_out;

    const int B = out_size;       // 32768 = 1024 * 32
    const int N = in_sizes[2];    // 256

    k_wprep<<<F4DIM, 128>>>((const float4*)coeffs, hw, N);
    k_main<<<(B + ROWS - 1) / ROWS, 256>>>(x, out, B);
}